// round 15
// baseline (speedup 1.0000x reference)
#include <cuda_runtime.h>
#include <cuda_fp16.h>
#include <math.h>
#include <stdint.h>

// ---------------- problem dims ----------------
#define BQ   1024
#define TT   64
#define HD   512
#define H3   1536
#define MGI  (BQ * TT)
#define KB   512                // K = 512 everywhere (fp16 A, fp16 W)
#define LN_EPS 1e-5f

// ---- big (gi) GEMM tiling ----
#define BK 32
#define KITERS (KB / BK)        // 16
#define SA 40
#define NSTAGE 4
#define BBM 128
#define BBN 128
#define BSTAGE ((BBM + BBN) * SA * 2)
#define BIG_SMEM (NSTAGE * BSTAGE)      // 81920

// ---- persistent loop tiling: 64x96, K=512, BK=64, 3 stages + gi buffer ----
#define LBM 64
#define LBN 96
#define LBK 64
#define LSA 72
#define LKIT (KB / LBK)                 // 8
#define LROWS (LBM + LBN)               // 160
#define LSTAGE (LROWS * LSA * 2)        // 23040
#define LNST 3
#define GI_OFF (LNST * LSTAGE)          // 69120
#define GISTR 100                       // fp32 stride (400B, 16B aligned)
#define LSMEM (GI_OFF + LBM * GISTR * 4) // 94720
#define PCTAS 256
#define NGRP 16                         // m-groups (16 CTAs each)

// ---------------- device scratch ----------------
__device__ __half g_Agi[(size_t)MGI * KB];
__device__ float  g_gi [(size_t)MGI * H3];     // gate-blocked cols, biases folded
__device__ __half g_Wih[(size_t)H3 * KB];      // gate-blocked rows, fp16
__device__ __half g_Whh[(size_t)H3 * KB];      // gate-blocked rows, fp16
__device__ __half g_hh[2][(size_t)BQ * KB];    // ping-pong fp16(h)
__device__ float  g_h [2][(size_t)BQ * HD];
__device__ float  g_bsum[H3];
__device__ int    g_perm[BQ];
__device__ int    g_sl[BQ];
__device__ int    g_nact[TT];
__device__ unsigned int g_gbar[NGRP];          // per-m-group barrier counters

// ---------------- helpers ----------------
__device__ __forceinline__ uint32_t smem_u32(const void* p) {
    uint32_t a;
    asm("{ .reg .u64 t; cvta.to.shared.u64 t, %1; cvt.u32.u64 %0, t; }" : "=r"(a) : "l"(p));
    return a;
}
#define CP_ASYNC16(dst, src) \
    asm volatile("cp.async.cg.shared.global [%0], [%1], 16;" :: "r"(dst), "l"(src))
#define CP_COMMIT() asm volatile("cp.async.commit_group;" ::: "memory")
#define CP_WAIT0()  asm volatile("cp.async.wait_group 0;" ::: "memory")
#define CP_WAIT1()  asm volatile("cp.async.wait_group 1;" ::: "memory")
#define CP_WAIT2()  asm volatile("cp.async.wait_group 2;" ::: "memory")

__device__ __forceinline__ void mma16816(float* c, const uint32_t* a,
                                         uint32_t b0, uint32_t b1)
{
    asm volatile(
        "mma.sync.aligned.m16n8k16.row.col.f32.f16.f16.f32 "
        "{%0,%1,%2,%3}, {%4,%5,%6,%7}, {%8,%9}, {%0,%1,%2,%3};"
        : "+f"(c[0]), "+f"(c[1]), "+f"(c[2]), "+f"(c[3])
        : "r"(a[0]), "r"(a[1]), "r"(a[2]), "r"(a[3]), "r"(b0), "r"(b1));
}
__device__ __forceinline__ void ldsm4(uint32_t* r, uint32_t addr) {
    asm volatile("ldmatrix.sync.aligned.m8n8.x4.shared.b16 {%0,%1,%2,%3}, [%4];"
                 : "=r"(r[0]), "=r"(r[1]), "=r"(r[2]), "=r"(r[3]) : "r"(addr));
}
__device__ __forceinline__ void ldsm2(uint32_t* r, uint32_t addr) {
    asm volatile("ldmatrix.sync.aligned.m8n8.x2.shared.b16 {%0,%1}, [%2];"
                 : "=r"(r[0]), "=r"(r[1]) : "r"(addr));
}
__device__ __forceinline__ unsigned ld_acq(const unsigned* p) {
    unsigned v;
    asm volatile("ld.acquire.gpu.global.u32 %0, [%1];" : "=r"(v) : "l"(p));
    return v;
}
__device__ __forceinline__ void red_add_release(unsigned* p) {
    asm volatile("red.release.gpu.global.add.u32 [%0], 1;" :: "l"(p) : "memory");
}
// Per-m-group barrier: 16 arrivals on one counter. IVALL-free (cross-CTA data
// flows via cp.async.cg / __ldcg L2 paths; own-CTA lines are L1-coherent).
__device__ __forceinline__ void group_bar(int grp, unsigned target) {
    __syncthreads();
    if (threadIdx.x == 0) {
        red_add_release(&g_gbar[grp]);
        while (ld_acq(&g_gbar[grp]) < target) {}
    }
    __syncthreads();
}
// gate-blocked column mapping: hidden i, gate g -> (i/32)*96 + g*32 + (i%32)
__device__ __forceinline__ int npmap(int i, int g) {
    return (i >> 5) * 96 + g * 32 + (i & 31);
}

// ===========================================================================
// sort rows by stop length (descending) -> g_perm, g_sl, g_nact. 1 CTA.
// ===========================================================================
__global__ void sort_kernel(const int* __restrict__ actions,
                            const int* __restrict__ stop_idx)
{
    __shared__ int counts[TT + 1];
    __shared__ int start[TT + 1];
    int tid = threadIdx.x;
    if (tid <= TT) counts[tid] = 0;
    __syncthreads();

    int si = stop_idx[tid];
    int sl = TT;
    for (int t = 0; t < TT; t++) {
        int a = actions[tid * TT + t];
        if (a < 0 || a == si) { sl = t; break; }
    }
    atomicAdd(&counts[sl], 1);
    __syncthreads();
    if (tid == 0) {
        int acc = 0;
        for (int s = TT; s >= 0; s--) { start[s] = acc; acc += counts[s]; }
        for (int t = 0; t < TT; t++) g_nact[t] = start[t];
        #pragma unroll
        for (int i = 0; i < NGRP; i++) g_gbar[i] = 0;
    }
    __syncthreads();
    int pos = atomicAdd(&start[sl], 1);
    g_perm[pos] = tid;
    g_sl[pos] = sl;
}

// ===========================================================================
// Big GEMM (gi): out[M, H3] = A x B^T + bias ; tile 128x128, K=512
// ===========================================================================
__global__ __launch_bounds__(256)
void gemm_big(const __half* __restrict__ A,
              const __half* __restrict__ B,
              const float* __restrict__ bias,
              float* __restrict__ out)
{
    const int col0 = blockIdx.x * BBN;
    const int row0 = blockIdx.y * BBM;
    if ((row0 & 1023) >= g_nact[row0 >> 10]) return;

    extern __shared__ __align__(16) char dsm[];
    const uint32_t sbase = smem_u32(dsm);

    const int tid  = threadIdx.x;
    const int lane = tid & 31;
    const int w    = tid >> 5;
    const int wr   = w & 1;
    const int wc   = w >> 1;
    const int qr   = lane >> 2;
    const int qc   = lane & 3;

    const __half* srcp[4];
    uint32_t soff[4];
    #pragma unroll
    for (int j = 0; j < 4; j++) {
        int idx  = tid + 256 * j;
        int arow = idx >> 2;
        int seg  = (idx & 3) * 8;
        if (arow < BBM) {
            srcp[j] = A + (size_t)(row0 + arow) * KB + seg;
            soff[j] = (uint32_t)(arow * SA + seg) * 2;
        } else {
            int brow = arow - BBM;
            srcp[j] = B + (size_t)(col0 + brow) * KB + seg;
            soff[j] = (uint32_t)((BBM + brow) * SA + seg) * 2;
        }
    }

    uint32_t aoff[4], boff[2];
    #pragma unroll
    for (int mi = 0; mi < 4; mi++)
        aoff[mi] = (uint32_t)((wr * 64 + mi * 16 + (lane & 7) + 8 * ((lane >> 3) & 1)) * SA
                              + 8 * (lane >> 4)) * 2;
    #pragma unroll
    for (int p = 0; p < 2; p++)
        boff[p] = (uint32_t)((BBM + wc * 32 + p * 16 + (lane & 7) + 8 * (lane >> 4)) * SA
                             + 8 * ((lane >> 3) & 1)) * 2;

    float acc[4][4][4];
    #pragma unroll
    for (int i = 0; i < 4; i++)
        #pragma unroll
        for (int j = 0; j < 4; j++)
            #pragma unroll
            for (int v = 0; v < 4; v++) acc[i][j][v] = 0.0f;

    #pragma unroll
    for (int s = 0; s < NSTAGE - 1; s++) {
        uint32_t sb = sbase + s * BSTAGE;
        #pragma unroll
        for (int j = 0; j < 4; j++) CP_ASYNC16(sb + soff[j], srcp[j] + s * BK);
        CP_COMMIT();
    }

    #pragma unroll 1
    for (int kt = 0; kt < KITERS; kt++) {
        if (kt < KITERS - 2)       CP_WAIT2();
        else if (kt == KITERS - 2) CP_WAIT1();
        else                       CP_WAIT0();
        __syncthreads();

        if (kt + NSTAGE - 1 < KITERS) {
            int kc = kt + NSTAGE - 1;
            uint32_t sb = sbase + (kc & (NSTAGE - 1)) * BSTAGE;
            #pragma unroll
            for (int j = 0; j < 4; j++) CP_ASYNC16(sb + soff[j], srcp[j] + kc * BK);
            CP_COMMIT();
        }

        uint32_t sst = sbase + (kt & (NSTAGE - 1)) * BSTAGE;
        #pragma unroll
        for (int ks = 0; ks < 2; ks++) {
            uint32_t kb2 = ks * 32;
            uint32_t af[4][4], bf[2][4];
            #pragma unroll
            for (int mi = 0; mi < 4; mi++) ldsm4(af[mi], sst + aoff[mi] + kb2);
            #pragma unroll
            for (int p = 0; p < 2; p++)    ldsm4(bf[p], sst + boff[p] + kb2);
            #pragma unroll
            for (int ni = 0; ni < 4; ni++) {
                uint32_t b0 = bf[ni >> 1][(ni & 1) * 2];
                uint32_t b1 = bf[ni >> 1][(ni & 1) * 2 + 1];
                #pragma unroll
                for (int mi = 0; mi < 4; mi++)
                    mma16816(acc[mi][ni], af[mi], b0, b1);
            }
        }
        __syncthreads();
    }

    #pragma unroll
    for (int mi = 0; mi < 4; mi++) {
        int r = row0 + wr * 64 + mi * 16 + qr;
        #pragma unroll
        for (int ni = 0; ni < 4; ni++) {
            int c = col0 + wc * 32 + ni * 8 + qc * 2;
            float2 bv = *(const float2*)(bias + c);
            float2 v0 = make_float2(acc[mi][ni][0] + bv.x, acc[mi][ni][1] + bv.y);
            float2 v1 = make_float2(acc[mi][ni][2] + bv.x, acc[mi][ni][3] + bv.y);
            *(float2*)(out + (size_t)r * H3 + c)       = v0;
            *(float2*)(out + (size_t)(r + 8) * H3 + c) = v1;
        }
    }
}

// ===========================================================================
// Persistent loop: 256 CTAs in 16 independent m-groups of 16 CTAs.
// All cross-CTA deps (h2, LN rows, hold) stay inside the m-group, so each
// group synchronizes only with itself (16-arrival barrier) and proceeds at
// its own pace across t. LN rows: CTA (mtile,ntile) emits row0+ntile*4..+3.
// ===========================================================================
__global__ __launch_bounds__(256, 2)
void persist_loop(const float* __restrict__ ln_w,
                  const float* __restrict__ ln_b,
                  const float* __restrict__ b_hh,
                  const float* __restrict__ gi,
                  float* __restrict__ out)
{
    extern __shared__ __align__(16) char dsm[];
    const uint32_t sbase = smem_u32(dsm);

    const int tid   = threadIdx.x;
    const int lane  = tid & 31;
    const int w     = tid >> 5;
    const int wr    = w & 1;        // m-warp
    const int wc    = w >> 1;       // n-warp
    const int qr    = lane >> 2;
    const int qc    = lane & 3;
    const int cid   = blockIdx.x;
    const int ntile = cid & 15;
    const int mtile = cid >> 4;
    const int row0  = mtile * LBM;
    const int col0  = ntile * LBN;
    const int hid0  = ntile * 32;

    // LN rows: within own m-group
    int orig_ln = 0, sl_ln = 0, rown = 0;
    if (w < 4) {
        rown    = row0 + ntile * 4 + w;
        orig_ln = g_perm[rown];
        sl_ln   = g_sl[rown];
    }

    // A/B loader mapping: 160 rows x 8 chunks = 1280 = 256 x 5
    size_t  goff[5];
    uint32_t soff[5];
    bool isA[5];
    #pragma unroll
    for (int j = 0; j < 5; j++) {
        int idx = tid + 256 * j;
        int row = idx >> 3;
        int seg = (idx & 7) * 8;
        isA[j] = (row < LBM);
        if (row < LBM) goff[j] = (size_t)(row0 + row) * KB + seg;
        else           goff[j] = (size_t)(col0 + row - LBM) * KB + seg;
        soff[j] = (uint32_t)(row * LSA + seg) * 2;
    }

    // gi loader: 64 rows x 24 chunks = 1536 = 256 x 6
    uint32_t gi_soff[6];
    size_t   gi_goff[6];
    #pragma unroll
    for (int j = 0; j < 6; j++) {
        int idx = tid + 256 * j;
        int rl  = idx / 24;
        int c   = idx - rl * 24;
        gi_soff[j] = (uint32_t)(GI_OFF + rl * (GISTR * 4) + c * 16);
        gi_goff[j] = (size_t)(row0 + rl) * H3 + col0 + c * 4;
    }

    uint32_t aoff[2];
    #pragma unroll
    for (int mi = 0; mi < 2; mi++)
        aoff[mi] = (uint32_t)((wr * 32 + mi * 16 + (lane & 7) + 8 * ((lane >> 3) & 1)) * LSA
                              + 8 * (lane >> 4)) * 2;
    uint32_t boffg[3];
    #pragma unroll
    for (int g = 0; g < 3; g++)
        boffg[g] = (uint32_t)((LBM + g * 32 + wc * 8 + (lane & 7)) * LSA
                              + 8 * ((lane >> 3) & 1)) * 2;

    #pragma unroll 1
    for (int t = 0; t < TT; t++) {
        const int cur = t & 1;
        const int nxt = cur ^ 1;
        const __half* hhcur = g_hh[cur];
        const int nact = g_nact[t];
        const bool tile_active = (row0 < nact) && (t < TT - 1);

        // issue gi prefetch (oldest group) + A/B prologue before LN
        if (tile_active) {
            const float* gib = gi + (size_t)t * BQ * H3;
            #pragma unroll
            for (int j = 0; j < 6; j++)
                CP_ASYNC16(sbase + gi_soff[j], gib + gi_goff[j]);
            CP_COMMIT();
            #pragma unroll
            for (int s = 0; s < LNST - 1; s++) {
                uint32_t sb = sbase + s * LSTAGE;
                #pragma unroll
                for (int j = 0; j < 5; j++) {
                    const __half* p = (isA[j] ? hhcur : g_Whh) + goff[j] + s * LBK;
                    CP_ASYNC16(sb + soff[j], p);
                }
                CP_COMMIT();
            }
        }

        // ---------- LN emit: warps 0..3, one row each (cross-CTA -> __ldcg) ----------
        if (w < 4) {
            int e = t < sl_ln ? t : sl_ln;
            const float4* hp = (const float4*)(g_h[e & 1] + (size_t)rown * HD);
            float4 v[4];
            #pragma unroll
            for (int j = 0; j < 4; j++) v[j] = __ldcg(hp + lane + 32 * j);
            float s = 0.0f;
            #pragma unroll
            for (int j = 0; j < 4; j++) s += v[j].x + v[j].y + v[j].z + v[j].w;
            #pragma unroll
            for (int o = 16; o > 0; o >>= 1) s += __shfl_xor_sync(0xffffffffu, s, o);
            float mean = s * (1.0f / HD);
            float q = 0.0f;
            #pragma unroll
            for (int j = 0; j < 4; j++) {
                float a0 = v[j].x - mean, a1 = v[j].y - mean;
                float a2 = v[j].z - mean, a3 = v[j].w - mean;
                q += a0 * a0 + a1 * a1 + a2 * a2 + a3 * a3;
            }
            #pragma unroll
            for (int o = 16; o > 0; o >>= 1) q += __shfl_xor_sync(0xffffffffu, q, o);
            float rstd = rsqrtf(q * (1.0f / HD) + LN_EPS);
            float* orow = out + ((size_t)orig_ln * TT + t) * HD;
            #pragma unroll
            for (int j = 0; j < 4; j++) {
                float4 lw = ((const float4*)ln_w)[lane + 32 * j];
                float4 lb = ((const float4*)ln_b)[lane + 32 * j];
                float4 o;
                o.x = (v[j].x - mean) * rstd * lw.x + lb.x;
                o.y = (v[j].y - mean) * rstd * lw.y + lb.y;
                o.z = (v[j].z - mean) * rstd * lw.z + lb.z;
                o.w = (v[j].w - mean) * rstd * lw.w + lb.w;
                ((float4*)orow)[lane + 32 * j] = o;
            }
        }
        if (t == TT - 1) break;

        if (tile_active) {
            // ---------- gh GEMM (64x96, K=512, BK=64, 3-stage) ----------
            float acc[2][3][4];
            #pragma unroll
            for (int i = 0; i < 2; i++)
                #pragma unroll
                for (int g = 0; g < 3; g++)
                    #pragma unroll
                    for (int v = 0; v < 4; v++) acc[i][g][v] = 0.0f;

            #pragma unroll 1
            for (int kt = 0; kt < LKIT; kt++) {
                if (kt < LKIT - 1) CP_WAIT1();
                else               CP_WAIT0();
                __syncthreads();   // also orders last iter's reads before refill below

                if (kt + LNST - 1 < LKIT) {
                    int kc = kt + LNST - 1;
                    uint32_t sb = sbase + (kc % LNST) * LSTAGE;
                    #pragma unroll
                    for (int j = 0; j < 5; j++) {
                        const __half* p = (isA[j] ? hhcur : g_Whh) + goff[j] + kc * LBK;
                        CP_ASYNC16(sb + soff[j], p);
                    }
                    CP_COMMIT();
                }

                uint32_t sstage = sbase + (kt % LNST) * LSTAGE;
                #pragma unroll
                for (int ks = 0; ks < 4; ks++) {
                    uint32_t kb2 = ks * 32;
                    uint32_t af[2][4];
                    ldsm4(af[0], sstage + aoff[0] + kb2);
                    ldsm4(af[1], sstage + aoff[1] + kb2);
                    #pragma unroll
                    for (int g = 0; g < 3; g++) {
                        uint32_t bf[2];
                        ldsm2(bf, sstage + boffg[g] + kb2);
                        mma16816(acc[0][g], af[0], bf[0], bf[1]);
                        mma16816(acc[1][g], af[1], bf[0], bf[1]);
                    }
                }
            }

            // ---------- fragment-resident GRU update (gi from smem) ----------
            const float* hcur = g_h[cur];
            float*  hnb  = g_h[nxt];
            __half* hhnb = g_hh[nxt];
            const float* gis = (const float*)(dsm + GI_OFF);
            #pragma unroll
            for (int mi = 0; mi < 2; mi++) {
                #pragma unroll
                for (int v = 0; v < 4; v++) {
                    int rl = wr * 32 + mi * 16 + qr + 8 * (v >> 1);
                    int b  = row0 + rl;
                    if (b >= nact) continue;
                    int jj = wc * 8 + qc * 2 + (v & 1);
                    int h  = hid0 + jj;
                    float gr = gis[rl * GISTR + jj];
                    float gz = gis[rl * GISTR + 32 + jj];
                    float gn = gis[rl * GISTR + 64 + jj];
                    float r = 1.0f / (1.0f + expf(-(gr + acc[mi][0][v])));
                    float z = 1.0f / (1.0f + expf(-(gz + acc[mi][1][v])));
                    float n = tanhf(gn + r * (acc[mi][2][v] + b_hh[1024 + h]));
                    float hold = hcur[(size_t)b * HD + h];
                    float hnew = (1.0f - z) * n + z * hold;
                    hnb[(size_t)b * HD + h]  = hnew;
                    hhnb[(size_t)b * KB + h] = __float2half_rn(hnew);
                }
            }
        }
        group_bar(mtile, (unsigned)(t + 1) * NGRP);
    }
}

// ===========================================================================
// prep kernels (gate-blocked np mapping)
// ===========================================================================
__global__ void prep_weights(const float* __restrict__ wih,
                             const float* __restrict__ whh)
{
    int n = blockIdx.x;
    int g = n >> 9, i = n & 511;
    int np = npmap(i, g);
    const float* src = (blockIdx.y == 0 ? wih : whh) + (size_t)n * HD;
    __half* dst = (blockIdx.y == 0 ? g_Wih : g_Whh) + (size_t)np * KB;
    for (int k = threadIdx.x; k < HD; k += 128)
        dst[k] = __float2half_rn(src[k]);
}

__global__ void prep_bias(const float* __restrict__ b_ih,
                          const float* __restrict__ b_hh)
{
    int x = blockIdx.x * 256 + threadIdx.x;
    if (x < H3) {
        int g = x >> 9, i = x & 511;
        g_bsum[npmap(i, g)] = b_ih[x] + (g < 2 ? b_hh[x] : 0.0f);
    }
}

__global__ void prep_agi(const int* __restrict__ actions,
                         const float* __restrict__ edge_tokens, int E)
{
    int m = blockIdx.x;
    int t = m >> 10, nb = m & (BQ - 1);
    if (nb >= g_nact[t]) return;
    int b = g_perm[nb];
    int a = actions[b * TT + t];
    a = a < 0 ? 0 : (a >= E ? E - 1 : a);
    const float* src = edge_tokens + (size_t)a * HD;
    __half* dst = g_Agi + (size_t)m * KB;
    for (int k = threadIdx.x; k < HD; k += 128)
        dst[k] = __float2half_rn(src[k]);
}

// ===========================================================================
// init
// ===========================================================================
__device__ __forceinline__ float block_sum_256(float v, float* red)
{
    int lane = threadIdx.x & 31, w = threadIdx.x >> 5;
    #pragma unroll
    for (int o = 16; o > 0; o >>= 1) v += __shfl_xor_sync(0xffffffffu, v, o);
    if (lane == 0) red[w] = v;
    __syncthreads();
    if (w == 0) {
        float x = (lane < 8) ? red[lane] : 0.0f;
        #pragma unroll
        for (int o = 4; o > 0; o >>= 1) x += __shfl_xor_sync(0xffffffffu, x, o);
        if (lane == 0) red[0] = x;
    }
    __syncthreads();
    float r = red[0];
    __syncthreads();
    return r;
}

__global__ void init_kernel(const float* __restrict__ question,
                            const float* __restrict__ node_tokens,
                            const int*   __restrict__ locals,
                            const int*   __restrict__ ptr,
                            const float* __restrict__ ln_w,
                            const float* __restrict__ ln_b)
{
    __shared__ float red[8];
    int nb = blockIdx.x, tid = threadIdx.x;
    int b = g_perm[nb];
    int p0 = ptr[b], p1 = ptr[b + 1];
    int cnt = p1 - p0;
    float inv = 1.0f / (float)(cnt > 0 ? cnt : 1);

    float s0 = 0.0f, s1 = 0.0f;
    for (int j = p0; j < p1; j++) {
        const float* nrow = node_tokens + (size_t)locals[j] * HD;
        s0 += nrow[tid]; s1 += nrow[tid + 256];
    }
    const float* q = question + (size_t)b * HD;
    float x0 = q[tid] + s0 * inv, x1 = q[tid + 256] + s1 * inv;

    float mean = block_sum_256(x0 + x1, red) * (1.0f / HD);
    float d0 = x0 - mean, d1 = x1 - mean;
    float var = block_sum_256(d0 * d0 + d1 * d1, red) * (1.0f / HD);
    float rstd = rsqrtf(var + LN_EPS);

    float v0 = d0 * rstd * ln_w[tid] + ln_b[tid];
    float v1 = d1 * rstd * ln_w[tid + 256] + ln_b[tid + 256];
    float* hrow = g_h[0] + (size_t)nb * HD;
    hrow[tid] = v0; hrow[tid + 256] = v1;

    __half* hhrow = g_hh[0] + (size_t)nb * KB;
    hhrow[tid]       = __float2half_rn(v0);
    hhrow[tid + 256] = __float2half_rn(v1);
}

// ===========================================================================
// launch
// ===========================================================================
extern "C" void kernel_launch(void* const* d_in, const int* in_sizes, int n_in,
                              void* d_out, int out_size)
{
    const int*   actions      = (const int*)  d_in[0];
    const float* edge_tokens  = (const float*)d_in[1];
    const int*   stop_indices = (const int*)  d_in[2];
    const float* question     = (const float*)d_in[3];
    const float* node_tokens  = (const float*)d_in[4];
    const int*   start_locals = (const int*)  d_in[5];
    const int*   start_ptr    = (const int*)  d_in[6];
    const float* w_ih         = (const float*)d_in[7];
    const float* w_hh         = (const float*)d_in[8];
    const float* b_ih         = (const float*)d_in[9];
    const float* b_hh         = (const float*)d_in[10];
    const float* ln_w         = (const float*)d_in[11];
    const float* ln_b         = (const float*)d_in[12];
    float* out = (float*)d_out;
    const int E = in_sizes[1] / HD;

    void *pAgi, *pWih, *pGi, *pBsum;
    cudaGetSymbolAddress(&pAgi, g_Agi);
    cudaGetSymbolAddress(&pWih, g_Wih);
    cudaGetSymbolAddress(&pGi,  g_gi);
    cudaGetSymbolAddress(&pBsum, g_bsum);

    cudaFuncSetAttribute(gemm_big, cudaFuncAttributeMaxDynamicSharedMemorySize, BIG_SMEM);
    cudaFuncSetAttribute(persist_loop, cudaFuncAttributeMaxDynamicSharedMemorySize, LSMEM);

    prep_weights<<<dim3(H3, 2), 128>>>(w_ih, w_hh);
    prep_bias<<<(H3 + 255) / 256, 256>>>(b_ih, b_hh);
    sort_kernel<<<1, 1024>>>(actions, stop_indices);
    prep_agi<<<MGI, 128>>>(actions, edge_tokens, E);
    init_kernel<<<BQ, 256>>>(question, node_tokens, start_locals, start_ptr, ln_w, ln_b);

    gemm_big<<<dim3(H3 / BBN, MGI / BBM), 256, BIG_SMEM>>>(
        (const __half*)pAgi, (const __half*)pWih,
        (const float*)pBsum, (float*)pGi);

    persist_loop<<<PCTAS, 256, LSMEM>>>(ln_w, ln_b, b_hh, (const float*)pGi, out);
}

// round 17
// speedup vs baseline: 1.2697x; 1.2697x over previous
#include <cuda_runtime.h>
#include <cuda_fp16.h>
#include <math.h>
#include <stdint.h>

// ---------------- problem dims ----------------
#define BQ   1024
#define TT   64
#define HD   512
#define H3   1536
#define MGI  (BQ * TT)
#define KB   512                // K = 512 everywhere (fp16 A, fp16 W)
#define LN_EPS 1e-5f

// ---- big (gi) GEMM tiling ----
#define BK 32
#define KITERS (KB / BK)        // 16
#define SA 40
#define NSTAGE 4
#define BBM 128
#define BBN 128
#define BSTAGE ((BBM + BBN) * SA * 2)
#define BIG_SMEM (NSTAGE * BSTAGE)      // 81920

// ---- persistent loop tiling: 64x96, K=512, BK=64, 3 stages + gi buffer ----
#define LBM 64
#define LBN 96
#define LBK 64
#define LSA 72
#define LKIT (KB / LBK)                 // 8
#define LROWS (LBM + LBN)               // 160
#define LSTAGE (LROWS * LSA * 2)        // 23040
#define LNST 3
#define GI_OFF (LNST * LSTAGE)          // 69120
#define GISTR 100                       // fp32 stride (400B, 16B aligned)
#define LSMEM (GI_OFF + LBM * GISTR * 4) // 94720
#define PCTAS 256

// ---------------- device scratch ----------------
__device__ __half g_Agi[(size_t)MGI * KB];
__device__ float  g_gi [(size_t)MGI * H3];     // gate-blocked cols, biases folded
__device__ __half g_Wih[(size_t)H3 * KB];      // gate-blocked rows, fp16
__device__ __half g_Whh[(size_t)H3 * KB];      // gate-blocked rows, fp16
__device__ __half g_hh[2][(size_t)BQ * KB];    // ping-pong fp16(h)
__device__ float  g_h [2][(size_t)BQ * HD];
__device__ float  g_bsum[H3];
__device__ int    g_perm[BQ];
__device__ int    g_sl[BQ];
__device__ int    g_nact[TT];
__device__ unsigned int g_barctr[8];

// ---------------- helpers ----------------
__device__ __forceinline__ uint32_t smem_u32(const void* p) {
    uint32_t a;
    asm("{ .reg .u64 t; cvta.to.shared.u64 t, %1; cvt.u32.u64 %0, t; }" : "=r"(a) : "l"(p));
    return a;
}
#define CP_ASYNC16(dst, src) \
    asm volatile("cp.async.cg.shared.global [%0], [%1], 16;" :: "r"(dst), "l"(src))
#define CP_COMMIT() asm volatile("cp.async.commit_group;" ::: "memory")
#define CP_WAIT0()  asm volatile("cp.async.wait_group 0;" ::: "memory")
#define CP_WAIT1()  asm volatile("cp.async.wait_group 1;" ::: "memory")
#define CP_WAIT2()  asm volatile("cp.async.wait_group 2;" ::: "memory")

__device__ __forceinline__ void mma16816(float* c, const uint32_t* a,
                                         uint32_t b0, uint32_t b1)
{
    asm volatile(
        "mma.sync.aligned.m16n8k16.row.col.f32.f16.f16.f32 "
        "{%0,%1,%2,%3}, {%4,%5,%6,%7}, {%8,%9}, {%0,%1,%2,%3};"
        : "+f"(c[0]), "+f"(c[1]), "+f"(c[2]), "+f"(c[3])
        : "r"(a[0]), "r"(a[1]), "r"(a[2]), "r"(a[3]), "r"(b0), "r"(b1));
}
__device__ __forceinline__ void ldsm4(uint32_t* r, uint32_t addr) {
    asm volatile("ldmatrix.sync.aligned.m8n8.x4.shared.b16 {%0,%1,%2,%3}, [%4];"
                 : "=r"(r[0]), "=r"(r[1]), "=r"(r[2]), "=r"(r[3]) : "r"(addr));
}
__device__ __forceinline__ void ldsm2(uint32_t* r, uint32_t addr) {
    asm volatile("ldmatrix.sync.aligned.m8n8.x2.shared.b16 {%0,%1}, [%2];"
                 : "=r"(r[0]), "=r"(r[1]) : "r"(addr));
}
__device__ __forceinline__ unsigned ld_acq(const unsigned* p) {
    unsigned v;
    asm volatile("ld.acquire.gpu.global.u32 %0, [%1];" : "=r"(v) : "l"(p));
    return v;
}
__device__ __forceinline__ void red_add_release(unsigned* p) {
    asm volatile("red.release.gpu.global.add.u32 [%0], 1;" :: "l"(p) : "memory");
}
// IVALL-free grid barrier (cross-CTA data flows via L2 paths only)
__device__ __forceinline__ void grid_bar(int cid, unsigned target) {
    __syncthreads();
    if (threadIdx.x == 0) {
        red_add_release(&g_barctr[cid & 7]);
        for (;;) {
            unsigned s = 0;
            #pragma unroll
            for (int i = 0; i < 8; i++) s += ld_acq(&g_barctr[i]);
            if (s >= target) break;
        }
    }
    __syncthreads();
}
// gate-blocked column mapping: hidden i, gate g -> (i/32)*96 + g*32 + (i%32)
__device__ __forceinline__ int npmap(int i, int g) {
    return (i >> 5) * 96 + g * 32 + (i & 31);
}

// ===========================================================================
// sort rows by stop length (descending) -> g_perm, g_sl, g_nact. 1 CTA.
// ===========================================================================
__global__ void sort_kernel(const int* __restrict__ actions,
                            const int* __restrict__ stop_idx)
{
    __shared__ int counts[TT + 1];
    __shared__ int start[TT + 1];
    int tid = threadIdx.x;
    if (tid <= TT) counts[tid] = 0;
    __syncthreads();

    int si = stop_idx[tid];
    int sl = TT;
    for (int t = 0; t < TT; t++) {
        int a = actions[tid * TT + t];
        if (a < 0 || a == si) { sl = t; break; }
    }
    atomicAdd(&counts[sl], 1);
    __syncthreads();
    if (tid == 0) {
        int acc = 0;
        for (int s = TT; s >= 0; s--) { start[s] = acc; acc += counts[s]; }
        for (int t = 0; t < TT; t++) g_nact[t] = start[t];
        #pragma unroll
        for (int i = 0; i < 8; i++) g_barctr[i] = 0;
    }
    __syncthreads();
    int pos = atomicAdd(&start[sl], 1);
    g_perm[pos] = tid;
    g_sl[pos] = sl;
}

// ===========================================================================
// Big GEMM (gi): out[M, H3] = A x B^T + bias ; tile 128x128, K=512
// ===========================================================================
__global__ __launch_bounds__(256)
void gemm_big(const __half* __restrict__ A,
              const __half* __restrict__ B,
              const float* __restrict__ bias,
              float* __restrict__ out)
{
    const int col0 = blockIdx.x * BBN;
    const int row0 = blockIdx.y * BBM;
    if ((row0 & 1023) >= g_nact[row0 >> 10]) return;

    extern __shared__ __align__(16) char dsm[];
    const uint32_t sbase = smem_u32(dsm);

    const int tid  = threadIdx.x;
    const int lane = tid & 31;
    const int w    = tid >> 5;
    const int wr   = w & 1;
    const int wc   = w >> 1;
    const int qr   = lane >> 2;
    const int qc   = lane & 3;

    const __half* srcp[4];
    uint32_t soff[4];
    #pragma unroll
    for (int j = 0; j < 4; j++) {
        int idx  = tid + 256 * j;
        int arow = idx >> 2;
        int seg  = (idx & 3) * 8;
        if (arow < BBM) {
            srcp[j] = A + (size_t)(row0 + arow) * KB + seg;
            soff[j] = (uint32_t)(arow * SA + seg) * 2;
        } else {
            int brow = arow - BBM;
            srcp[j] = B + (size_t)(col0 + brow) * KB + seg;
            soff[j] = (uint32_t)((BBM + brow) * SA + seg) * 2;
        }
    }

    uint32_t aoff[4], boff[2];
    #pragma unroll
    for (int mi = 0; mi < 4; mi++)
        aoff[mi] = (uint32_t)((wr * 64 + mi * 16 + (lane & 7) + 8 * ((lane >> 3) & 1)) * SA
                              + 8 * (lane >> 4)) * 2;
    #pragma unroll
    for (int p = 0; p < 2; p++)
        boff[p] = (uint32_t)((BBM + wc * 32 + p * 16 + (lane & 7) + 8 * (lane >> 4)) * SA
                             + 8 * ((lane >> 3) & 1)) * 2;

    float acc[4][4][4];
    #pragma unroll
    for (int i = 0; i < 4; i++)
        #pragma unroll
        for (int j = 0; j < 4; j++)
            #pragma unroll
            for (int v = 0; v < 4; v++) acc[i][j][v] = 0.0f;

    #pragma unroll
    for (int s = 0; s < NSTAGE - 1; s++) {
        uint32_t sb = sbase + s * BSTAGE;
        #pragma unroll
        for (int j = 0; j < 4; j++) CP_ASYNC16(sb + soff[j], srcp[j] + s * BK);
        CP_COMMIT();
    }

    #pragma unroll 1
    for (int kt = 0; kt < KITERS; kt++) {
        if (kt < KITERS - 2)       CP_WAIT2();
        else if (kt == KITERS - 2) CP_WAIT1();
        else                       CP_WAIT0();
        __syncthreads();   // orders prior-iter reads before this iter's refill

        if (kt + NSTAGE - 1 < KITERS) {
            int kc = kt + NSTAGE - 1;
            uint32_t sb = sbase + (kc & (NSTAGE - 1)) * BSTAGE;
            #pragma unroll
            for (int j = 0; j < 4; j++) CP_ASYNC16(sb + soff[j], srcp[j] + kc * BK);
            CP_COMMIT();
        }

        uint32_t sst = sbase + (kt & (NSTAGE - 1)) * BSTAGE;
        #pragma unroll
        for (int ks = 0; ks < 2; ks++) {
            uint32_t kb2 = ks * 32;
            uint32_t af[4][4], bf[2][4];
            #pragma unroll
            for (int mi = 0; mi < 4; mi++) ldsm4(af[mi], sst + aoff[mi] + kb2);
            #pragma unroll
            for (int p = 0; p < 2; p++)    ldsm4(bf[p], sst + boff[p] + kb2);
            #pragma unroll
            for (int ni = 0; ni < 4; ni++) {
                uint32_t b0 = bf[ni >> 1][(ni & 1) * 2];
                uint32_t b1 = bf[ni >> 1][(ni & 1) * 2 + 1];
                #pragma unroll
                for (int mi = 0; mi < 4; mi++)
                    mma16816(acc[mi][ni], af[mi], b0, b1);
            }
        }
    }

    #pragma unroll
    for (int mi = 0; mi < 4; mi++) {
        int r = row0 + wr * 64 + mi * 16 + qr;
        #pragma unroll
        for (int ni = 0; ni < 4; ni++) {
            int c = col0 + wc * 32 + ni * 8 + qc * 2;
            float2 bv = *(const float2*)(bias + c);
            float2 v0 = make_float2(acc[mi][ni][0] + bv.x, acc[mi][ni][1] + bv.y);
            float2 v1 = make_float2(acc[mi][ni][2] + bv.x, acc[mi][ni][3] + bv.y);
            *(float2*)(out + (size_t)r * H3 + c)       = v0;
            *(float2*)(out + (size_t)(r + 8) * H3 + c) = v1;
        }
    }
}

// ===========================================================================
// Persistent loop: 256 CTAs (2/SM), tile 64x96, K=512, BK=64, 3-stage.
// Fragment-resident GRU epilogue. gi(t+1) prefetched during step t's tail
// (barrier + next LN hide its DRAM latency); gi stays the oldest group.
// ===========================================================================
__global__ __launch_bounds__(256, 2)
void persist_loop(const float* __restrict__ ln_w,
                  const float* __restrict__ ln_b,
                  const float* __restrict__ b_hh,
                  const float* __restrict__ gi,
                  float* __restrict__ out)
{
    extern __shared__ __align__(16) char dsm[];
    const uint32_t sbase = smem_u32(dsm);

    const int tid   = threadIdx.x;
    const int lane  = tid & 31;
    const int w     = tid >> 5;
    const int wr    = w & 1;        // m-warp
    const int wc    = w >> 1;       // n-warp
    const int qr    = lane >> 2;
    const int qc    = lane & 3;
    const int cid   = blockIdx.x;
    const int ntile = cid & 15;
    const int mtile = cid >> 4;
    const int row0  = mtile * LBM;
    const int col0  = ntile * LBN;
    const int hid0  = ntile * 32;

    int orig_ln = 0, sl_ln = 0;
    if (w < 4) {
        orig_ln = g_perm[cid * 4 + w];
        sl_ln   = g_sl[cid * 4 + w];
    }

    // A/B loader mapping: 160 rows x 8 chunks = 1280 = 256 x 5
    size_t  goff[5];
    uint32_t soff[5];
    bool isA[5];
    #pragma unroll
    for (int j = 0; j < 5; j++) {
        int idx = tid + 256 * j;
        int row = idx >> 3;
        int seg = (idx & 7) * 8;
        isA[j] = (row < LBM);
        if (row < LBM) goff[j] = (size_t)(row0 + row) * KB + seg;
        else           goff[j] = (size_t)(col0 + row - LBM) * KB + seg;
        soff[j] = (uint32_t)(row * LSA + seg) * 2;
    }

    // gi loader: 64 rows x 24 chunks = 1536 = 256 x 6
    uint32_t gi_soff[6];
    size_t   gi_goff[6];
    #pragma unroll
    for (int j = 0; j < 6; j++) {
        int idx = tid + 256 * j;
        int rl  = idx / 24;
        int c   = idx - rl * 24;
        gi_soff[j] = (uint32_t)(GI_OFF + rl * (GISTR * 4) + c * 16);
        gi_goff[j] = (size_t)(row0 + rl) * H3 + col0 + c * 4;
    }

    uint32_t aoff[2];
    #pragma unroll
    for (int mi = 0; mi < 2; mi++)
        aoff[mi] = (uint32_t)((wr * 32 + mi * 16 + (lane & 7) + 8 * ((lane >> 3) & 1)) * LSA
                              + 8 * (lane >> 4)) * 2;
    uint32_t boffg[3];
    #pragma unroll
    for (int g = 0; g < 3; g++)
        boffg[g] = (uint32_t)((LBM + g * 32 + wc * 8 + (lane & 7)) * LSA
                              + 8 * ((lane >> 3) & 1)) * 2;

    unsigned ph = 0;

    // prefetch gi for t=0 (oldest cp.async group)
    if (row0 < g_nact[0]) {
        #pragma unroll
        for (int j = 0; j < 6; j++)
            CP_ASYNC16(sbase + gi_soff[j], gi + gi_goff[j]);
        CP_COMMIT();
    }

    #pragma unroll 1
    for (int t = 0; t < TT; t++) {
        const int cur = t & 1;
        const int nxt = cur ^ 1;
        const __half* hhcur = g_hh[cur];
        const int nact = g_nact[t];
        const bool tile_active = (row0 < nact) && (t < TT - 1);

        // issue A/B prologue before LN (gi already in flight)
        if (tile_active) {
            #pragma unroll
            for (int s = 0; s < LNST - 1; s++) {
                uint32_t sb = sbase + s * LSTAGE;
                #pragma unroll
                for (int j = 0; j < 5; j++) {
                    const __half* p = (isA[j] ? hhcur : g_Whh) + goff[j] + s * LBK;
                    CP_ASYNC16(sb + soff[j], p);
                }
                CP_COMMIT();
            }
        }

        // ---------- LN emit: warps 0..3, one row each (cross-CTA -> __ldcg) ----------
        if (w < 4) {
            int rown = cid * 4 + w;
            int e = t < sl_ln ? t : sl_ln;
            const float4* hp = (const float4*)(g_h[e & 1] + (size_t)rown * HD);
            float4 v[4];
            #pragma unroll
            for (int j = 0; j < 4; j++) v[j] = __ldcg(hp + lane + 32 * j);
            float s = 0.0f;
            #pragma unroll
            for (int j = 0; j < 4; j++) s += v[j].x + v[j].y + v[j].z + v[j].w;
            #pragma unroll
            for (int o = 16; o > 0; o >>= 1) s += __shfl_xor_sync(0xffffffffu, s, o);
            float mean = s * (1.0f / HD);
            float q = 0.0f;
            #pragma unroll
            for (int j = 0; j < 4; j++) {
                float a0 = v[j].x - mean, a1 = v[j].y - mean;
                float a2 = v[j].z - mean, a3 = v[j].w - mean;
                q += a0 * a0 + a1 * a1 + a2 * a2 + a3 * a3;
            }
            #pragma unroll
            for (int o = 16; o > 0; o >>= 1) q += __shfl_xor_sync(0xffffffffu, q, o);
            float rstd = rsqrtf(q * (1.0f / HD) + LN_EPS);
            float* orow = out + ((size_t)orig_ln * TT + t) * HD;
            #pragma unroll
            for (int j = 0; j < 4; j++) {
                float4 lw = ((const float4*)ln_w)[lane + 32 * j];
                float4 lb = ((const float4*)ln_b)[lane + 32 * j];
                float4 o;
                o.x = (v[j].x - mean) * rstd * lw.x + lb.x;
                o.y = (v[j].y - mean) * rstd * lw.y + lb.y;
                o.z = (v[j].z - mean) * rstd * lw.z + lb.z;
                o.w = (v[j].w - mean) * rstd * lw.w + lb.w;
                ((float4*)orow)[lane + 32 * j] = o;
            }
        }
        if (t == TT - 1) break;

        if (tile_active) {
            // ---------- gh GEMM (64x96, K=512, BK=64, 3-stage) ----------
            float acc[2][3][4];
            #pragma unroll
            for (int i = 0; i < 2; i++)
                #pragma unroll
                for (int g = 0; g < 3; g++)
                    #pragma unroll
                    for (int v = 0; v < 4; v++) acc[i][g][v] = 0.0f;

            #pragma unroll 1
            for (int kt = 0; kt < LKIT; kt++) {
                if (kt < LKIT - 1) CP_WAIT1();
                else               CP_WAIT0();
                __syncthreads();   // orders prior-iter reads before this iter's refill

                if (kt + LNST - 1 < LKIT) {
                    int kc = kt + LNST - 1;
                    uint32_t sb = sbase + (kc % LNST) * LSTAGE;
                    #pragma unroll
                    for (int j = 0; j < 5; j++) {
                        const __half* p = (isA[j] ? hhcur : g_Whh) + goff[j] + kc * LBK;
                        CP_ASYNC16(sb + soff[j], p);
                    }
                    CP_COMMIT();
                }

                uint32_t sstage = sbase + (kt % LNST) * LSTAGE;
                #pragma unroll
                for (int ks = 0; ks < 4; ks++) {
                    uint32_t kb2 = ks * 32;
                    uint32_t af[2][4];
                    ldsm4(af[0], sstage + aoff[0] + kb2);
                    ldsm4(af[1], sstage + aoff[1] + kb2);
                    #pragma unroll
                    for (int g = 0; g < 3; g++) {
                        uint32_t bf[2];
                        ldsm2(bf, sstage + boffg[g] + kb2);
                        mma16816(acc[0][g], af[0], bf[0], bf[1]);
                        mma16816(acc[1][g], af[1], bf[0], bf[1]);
                    }
                }
            }

            // ---------- fragment-resident GRU update (gi from smem) ----------
            const float* hcur = g_h[cur];
            float*  hnb  = g_h[nxt];
            __half* hhnb = g_hh[nxt];
            const float* gis = (const float*)(dsm + GI_OFF);
            #pragma unroll
            for (int mi = 0; mi < 2; mi++) {
                #pragma unroll
                for (int v = 0; v < 4; v++) {
                    int rl = wr * 32 + mi * 16 + qr + 8 * (v >> 1);
                    int b  = row0 + rl;
                    if (b >= nact) continue;
                    int jj = wc * 8 + qc * 2 + (v & 1);
                    int h  = hid0 + jj;
                    float gr = gis[rl * GISTR + jj];
                    float gz = gis[rl * GISTR + 32 + jj];
                    float gn = gis[rl * GISTR + 64 + jj];
                    float r = 1.0f / (1.0f + expf(-(gr + acc[mi][0][v])));
                    float z = 1.0f / (1.0f + expf(-(gz + acc[mi][1][v])));
                    float n = tanhf(gn + r * (acc[mi][2][v] + b_hh[1024 + h]));
                    float hold = hcur[(size_t)b * HD + h];
                    float hnew = (1.0f - z) * n + z * hold;
                    hnb[(size_t)b * HD + h]  = hnew;
                    hhnb[(size_t)b * KB + h] = __float2half_rn(hnew);
                }
            }

            // prefetch gi for t+1 during barrier/LN window (gi is static data)
            __syncthreads();   // all gi smem reads done before overwrite
            if (row0 < g_nact[t + 1] && t + 1 < TT - 1) {
                const float* gib = gi + (size_t)(t + 1) * BQ * H3;
                #pragma unroll
                for (int j = 0; j < 6; j++)
                    CP_ASYNC16(sbase + gi_soff[j], gib + gi_goff[j]);
                CP_COMMIT();
            }
        }
        grid_bar(cid, ++ph * PCTAS);
    }
}

// ===========================================================================
// prep kernels (gate-blocked np mapping)
// ===========================================================================
__global__ void prep_weights(const float* __restrict__ wih,
                             const float* __restrict__ whh)
{
    int n = blockIdx.x;
    int g = n >> 9, i = n & 511;
    int np = npmap(i, g);
    const float* src = (blockIdx.y == 0 ? wih : whh) + (size_t)n * HD;
    __half* dst = (blockIdx.y == 0 ? g_Wih : g_Whh) + (size_t)np * KB;
    for (int k = threadIdx.x; k < HD; k += 128)
        dst[k] = __float2half_rn(src[k]);
}

__global__ void prep_bias(const float* __restrict__ b_ih,
                          const float* __restrict__ b_hh)
{
    int x = blockIdx.x * 256 + threadIdx.x;
    if (x < H3) {
        int g = x >> 9, i = x & 511;
        g_bsum[npmap(i, g)] = b_ih[x] + (g < 2 ? b_hh[x] : 0.0f);
    }
}

__global__ void prep_agi(const int* __restrict__ actions,
                         const float* __restrict__ edge_tokens, int E)
{
    int m = blockIdx.x;
    int t = m >> 10, nb = m & (BQ - 1);
    if (nb >= g_nact[t]) return;
    int b = g_perm[nb];
    int a = actions[b * TT + t];
    a = a < 0 ? 0 : (a >= E ? E - 1 : a);
    const float* src = edge_tokens + (size_t)a * HD;
    __half* dst = g_Agi + (size_t)m * KB;
    for (int k = threadIdx.x; k < HD; k += 128)
        dst[k] = __float2half_rn(src[k]);
}

// ===========================================================================
// init
// ===========================================================================
__device__ __forceinline__ float block_sum_256(float v, float* red)
{
    int lane = threadIdx.x & 31, w = threadIdx.x >> 5;
    #pragma unroll
    for (int o = 16; o > 0; o >>= 1) v += __shfl_xor_sync(0xffffffffu, v, o);
    if (lane == 0) red[w] = v;
    __syncthreads();
    if (w == 0) {
        float x = (lane < 8) ? red[lane] : 0.0f;
        #pragma unroll
        for (int o = 4; o > 0; o >>= 1) x += __shfl_xor_sync(0xffffffffu, x, o);
        if (lane == 0) red[0] = x;
    }
    __syncthreads();
    float r = red[0];
    __syncthreads();
    return r;
}

__global__ void init_kernel(const float* __restrict__ question,
                            const float* __restrict__ node_tokens,
                            const int*   __restrict__ locals,
                            const int*   __restrict__ ptr,
                            const float* __restrict__ ln_w,
                            const float* __restrict__ ln_b)
{
    __shared__ float red[8];
    int nb = blockIdx.x, tid = threadIdx.x;
    int b = g_perm[nb];
    int p0 = ptr[b], p1 = ptr[b + 1];
    int cnt = p1 - p0;
    float inv = 1.0f / (float)(cnt > 0 ? cnt : 1);

    float s0 = 0.0f, s1 = 0.0f;
    for (int j = p0; j < p1; j++) {
        const float* nrow = node_tokens + (size_t)locals[j] * HD;
        s0 += nrow[tid]; s1 += nrow[tid + 256];
    }
    const float* q = question + (size_t)b * HD;
    float x0 = q[tid] + s0 * inv, x1 = q[tid + 256] + s1 * inv;

    float mean = block_sum_256(x0 + x1, red) * (1.0f / HD);
    float d0 = x0 - mean, d1 = x1 - mean;
    float var = block_sum_256(d0 * d0 + d1 * d1, red) * (1.0f / HD);
    float rstd = rsqrtf(var + LN_EPS);

    float v0 = d0 * rstd * ln_w[tid] + ln_b[tid];
    float v1 = d1 * rstd * ln_w[tid + 256] + ln_b[tid + 256];
    float* hrow = g_h[0] + (size_t)nb * HD;
    hrow[tid] = v0; hrow[tid + 256] = v1;

    __half* hhrow = g_hh[0] + (size_t)nb * KB;
    hhrow[tid]       = __float2half_rn(v0);
    hhrow[tid + 256] = __float2half_rn(v1);
}

// ===========================================================================
// launch
// ===========================================================================
extern "C" void kernel_launch(void* const* d_in, const int* in_sizes, int n_in,
                              void* d_out, int out_size)
{
    const int*   actions      = (const int*)  d_in[0];
    const float* edge_tokens  = (const float*)d_in[1];
    const int*   stop_indices = (const int*)  d_in[2];
    const float* question     = (const float*)d_in[3];
    const float* node_tokens  = (const float*)d_in[4];
    const int*   start_locals = (const int*)  d_in[5];
    const int*   start_ptr    = (const int*)  d_in[6];
    const float* w_ih         = (const float*)d_in[7];
    const float* w_hh         = (const float*)d_in[8];
    const float* b_ih         = (const float*)d_in[9];
    const float* b_hh         = (const float*)d_in[10];
    const float* ln_w         = (const float*)d_in[11];
    const float* ln_b         = (const float*)d_in[12];
    float* out = (float*)d_out;
    const int E = in_sizes[1] / HD;

    void *pAgi, *pWih, *pGi, *pBsum;
    cudaGetSymbolAddress(&pAgi, g_Agi);
    cudaGetSymbolAddress(&pWih, g_Wih);
    cudaGetSymbolAddress(&pGi,  g_gi);
    cudaGetSymbolAddress(&pBsum, g_bsum);

    cudaFuncSetAttribute(gemm_big, cudaFuncAttributeMaxDynamicSharedMemorySize, BIG_SMEM);
    cudaFuncSetAttribute(persist_loop, cudaFuncAttributeMaxDynamicSharedMemorySize, LSMEM);

    prep_weights<<<dim3(H3, 2), 128>>>(w_ih, w_hh);
    prep_bias<<<(H3 + 255) / 256, 256>>>(b_ih, b_hh);
    sort_kernel<<<1, 1024>>>(actions, stop_indices);
    prep_agi<<<MGI, 128>>>(actions, edge_tokens, E);
    init_kernel<<<BQ, 256>>>(question, node_tokens, start_locals, start_ptr, ln_w, ln_b);

    gemm_big<<<dim3(H3 / BBN, MGI / BBM), 256, BIG_SMEM>>>(
        (const __half*)pAgi, (const __half*)pWih,
        (const float*)pBsum, (float*)pGi);

    persist_loop<<<PCTAS, 256, LSMEM>>>(ln_w, ln_b, b_hh, (const float*)pGi, out);
}